// round 11
// baseline (speedup 1.0000x reference)
#include <cuda_runtime.h>
#include <cuda_fp16.h>
#include <cstdint>

#define NN   100000
#define FC   128
#define NE   1600000
#define NG   512
#define NOUT 10
#define NSCAN (NN + 1)
#define SCAN_BLK 1024
#define NBLK ((NSCAN + SCAN_BLK - 1) / SCAN_BLK)   // 98

// Scratch (device globals)
__device__ uint2  g_f16a [(size_t)NN * 32];   // fp16 features ping
__device__ uint2  g_f16b [(size_t)NN * 32];   // fp16 features pong
__device__ float4 g_ha   [(size_t)NN * (FC / 4)];   // fp32 layer-3 output
__device__ int    g_rowptr[NSCAN];
__device__ int    g_cursor[NN];
__device__ int    g_esrc[NE];
__device__ int    g_part[NBLK];
__device__ int    g_is64;

// ---------------------------------------------------------------------------
// Index dtype detection (int32 vs int64 edge/batch buffers)
// ---------------------------------------------------------------------------
__global__ void detect_kernel(const long long* __restrict__ ei)
{
    __shared__ int ok;
    if (threadIdx.x == 0) ok = 1;
    __syncthreads();
    long long v = ei[threadIdx.x];           // 512 threads
    if (v < 0 || v >= NN) atomicAnd(&ok, 0);
    __syncthreads();
    if (threadIdx.x == 0) g_is64 = ok;
}

__device__ __forceinline__ long long load_idx(const void* base, int i, int is64)
{
    if (is64) return ((const long long*)base)[i];
    return (long long)((const int*)base)[i];
}

// ---------------------------------------------------------------------------
// CSR build: histogram -> scan -> fill
// ---------------------------------------------------------------------------
__global__ void hist_kernel(const void* __restrict__ ei, int* __restrict__ deg)
{
    int is64 = g_is64;
    for (int e = blockIdx.x * blockDim.x + threadIdx.x; e < NE;
         e += gridDim.x * blockDim.x) {
        int d = (int)load_idx(ei, e + NE, is64);
        atomicAdd(&deg[d + 1], 1);
    }
}

__global__ void scanA_kernel(int* __restrict__ deg, int* __restrict__ part)
{
    __shared__ int sm[SCAN_BLK];
    int tid = threadIdx.x;
    int i = blockIdx.x * SCAN_BLK + tid;
    int v = (i < NSCAN) ? deg[i] : 0;
    sm[tid] = v;
    __syncthreads();
#pragma unroll
    for (int off = 1; off < SCAN_BLK; off <<= 1) {
        int t = (tid >= off) ? sm[tid - off] : 0;
        __syncthreads();
        sm[tid] += t;
        __syncthreads();
    }
    if (i < NSCAN) deg[i] = sm[tid];
    if (tid == SCAN_BLK - 1) part[blockIdx.x] = sm[tid];
}

// scanC also folds the cross-block partial prefix (98 partials) in-kernel.
__global__ void scanC_kernel(int* __restrict__ deg, const int* __restrict__ part,
                             int* __restrict__ cursor)
{
    __shared__ int soff;
    if (threadIdx.x == 0) soff = 0;
    __syncthreads();
    if (threadIdx.x < blockIdx.x)          // blockIdx.x <= 97 < blockDim
        atomicAdd(&soff, part[threadIdx.x]);
    __syncthreads();
    int i = blockIdx.x * SCAN_BLK + threadIdx.x;
    if (i < NSCAN) {
        int v = deg[i] + soff;
        deg[i] = v;
        if (i < NN) cursor[i] = v;
    }
}

__global__ void fill_kernel(const void* __restrict__ ei,
                            int* __restrict__ cursor, int* __restrict__ esrc)
{
    int is64 = g_is64;
    for (int e = blockIdx.x * blockDim.x + threadIdx.x; e < NE;
         e += gridDim.x * blockDim.x) {
        int s = (int)load_idx(ei, e, is64);
        int d = (int)load_idx(ei, e + NE, is64);
        int pos = atomicAdd(&cursor[d], 1);
        esrc[pos] = s;
    }
}

// ---------------------------------------------------------------------------
// fp32 -> fp16 convert
// ---------------------------------------------------------------------------
__global__ void cvt16_kernel(const float4* __restrict__ src, uint2* __restrict__ dst)
{
    int i = blockIdx.x * blockDim.x + threadIdx.x;
    if (i >= NN * 32) return;
    float4 v = src[i];
    uint2 o;
    *(__half2*)&o.x = __floats2half2_rn(v.x, v.y);
    *(__half2*)&o.y = __floats2half2_rn(v.z, v.w);
    dst[i] = o;
}

// ---------------------------------------------------------------------------
// FUSED gather + fp16 tensor-core GraphConv:
//   out = (relu?)([segsum(xh) | xh] @ [Wrel;Wroot] + b)
// Phase 1: each warp gathers 16 rows of agg into sAgg (fp32 accum, fp16 store).
// Phase 2: K=256 GEMM; chunks 0-3 read sAgg (sync-free), 4-7 stage X.
// 2 blocks/SM (110KB smem each).
// ---------------------------------------------------------------------------
#define WS2 132                  // weight stride (words); 132 % 32 == 4
#define AGS 68                   // sAgg stride (words);   68 % 32 == 4
#define AS2 20                   // sX stride (words);     20 % 32 == 20
#define SWH_WORDS (128 * WS2)    // 16896
#define SAG_WORDS (128 * AGS)    //  8704
#define SAX_WORDS (128 * AS2)    //  2560
#define GC_SMEM_BYTES ((SWH_WORDS + SAG_WORDS + SAX_WORDS) * 4)   // 112640

__device__ __forceinline__ void mma_f16(float c[4],
                                        uint32_t a0, uint32_t a1,
                                        uint32_t a2, uint32_t a3,
                                        uint32_t b0, uint32_t b1)
{
    asm volatile("mma.sync.aligned.m16n8k16.row.col.f32.f16.f16.f32 "
                 "{%0,%1,%2,%3}, {%4,%5,%6,%7}, {%8,%9}, {%0,%1,%2,%3};"
                 : "+f"(c[0]), "+f"(c[1]), "+f"(c[2]), "+f"(c[3])
                 : "r"(a0), "r"(a1), "r"(a2), "r"(a3), "r"(b0), "r"(b1));
}

__global__ __launch_bounds__(256, 2) void gconv_fused_kernel(
    const uint2* __restrict__ xh,          // fp16 features (gather + root)
    const int* __restrict__ rowptr,
    const int* __restrict__ esrc,
    const float* __restrict__ Wrel, const float* __restrict__ Wroot,
    const float* __restrict__ bias, float* __restrict__ out32,
    uint32_t* __restrict__ out16, int do_relu)
{
    extern __shared__ uint32_t smw[];
    uint32_t* sW   = smw;                        // [k2 0..127][n 0..127] stride 132
    uint32_t* sAgg = smw + SWH_WORDS;            // [row 0..127][k2 0..63] stride 68
    uint32_t* sX   = smw + SWH_WORDS + SAG_WORDS;// [row 0..127][k2 0..15] stride 20

    const int tid  = threadIdx.x;
    const int warp = tid >> 5;
    const int lane = tid & 31;
    const int rowBase = blockIdx.x * 128;

    const int wm = (warp & 3) * 32;   // warp rows [wm, wm+32)
    const int wn = (warp >> 2) * 64;  // warp cols [wn, wn+64)
    const int g8 = lane >> 2;
    const int ak = lane & 3;

    // ---- Stage stacked weights as half2(k even, k odd) ----
    for (int i = tid; i < 4096; i += 256) {
        int k2 = i >> 5;          // 0..127
        int n4 = i & 31;
        const float* r0 = (k2 < 64) ? &Wrel[(2 * k2) * FC + n4 * 4]
                                    : &Wroot[(2 * k2 - 128) * FC + n4 * 4];
        float4 w0 = *(const float4*)r0;
        float4 w1 = *(const float4*)(r0 + FC);
        uint32_t* d = &sW[k2 * WS2 + n4 * 4];
        *(__half2*)&d[0] = __floats2half2_rn(w0.x, w1.x);
        *(__half2*)&d[1] = __floats2half2_rn(w0.y, w1.y);
        *(__half2*)&d[2] = __floats2half2_rn(w0.z, w1.z);
        *(__half2*)&d[3] = __floats2half2_rn(w0.w, w1.w);
    }

    // ---- Phase 1: gather agg for this block's 128 rows into sAgg ----
    // Warp w owns rows [w*16, w*16+16). Lane c covers channels [4c, 4c+4).
#pragma unroll 1
    for (int r = 0; r < 16; r++) {
        int row  = warp * 16 + r;
        int grow = rowBase + row;
        float4 a = make_float4(0.f, 0.f, 0.f, 0.f);
        if (grow < NN) {
            int lo = __ldg(&rowptr[grow]);
            int hi = __ldg(&rowptr[grow + 1]);
            int j = lo;
            for (; j + 8 <= hi; j += 8) {       // MLP=8 against L2 latency
                uint2 v[8];
#pragma unroll
                for (int k = 0; k < 8; k++) {
                    int s = __ldg(&esrc[j + k]);
                    v[k] = xh[(size_t)s * 32 + lane];
                }
#pragma unroll
                for (int k = 0; k < 8; k++) {
                    float2 p0 = __half22float2(*(__half2*)&v[k].x);
                    float2 p1 = __half22float2(*(__half2*)&v[k].y);
                    a.x += p0.x; a.y += p0.y; a.z += p1.x; a.w += p1.y;
                }
            }
            for (; j < hi; j++) {
                int s = __ldg(&esrc[j]);
                uint2 v = xh[(size_t)s * 32 + lane];
                float2 p0 = __half22float2(*(__half2*)&v.x);
                float2 p1 = __half22float2(*(__half2*)&v.y);
                a.x += p0.x; a.y += p0.y; a.z += p1.x; a.w += p1.y;
            }
        }
        uint2 o;
        *(__half2*)&o.x = __floats2half2_rn(a.x, a.y);
        *(__half2*)&o.y = __floats2half2_rn(a.z, a.w);
        *(uint2*)&sAgg[row * AGS + lane * 2] = o;
    }
    __syncthreads();

    // ---- Phase 2: K=256 GEMM ----
    float acc[2][8][4];
#pragma unroll
    for (int t = 0; t < 2; t++)
#pragma unroll
        for (int j = 0; j < 8; j++)
#pragma unroll
            for (int q = 0; q < 4; q++) acc[t][j][q] = 0.f;

    const int arG = (wm + g8) * AGS;
    const int arX = (wm + g8) * AS2;
    const uint4* Xh4 = (const uint4*)xh;

    uint4 pf[2];
#pragma unroll 1
    for (int c = 0; c < 8; c++) {
        // prefetch next X chunk (chunks 4..7 come from global X)
        if (c >= 3 && c < 7) {
            int cq = (c + 1 - 4) * 4;
#pragma unroll
            for (int r = 0; r < 2; r++) {
                int idx = tid + r * 256;
                int row = idx >> 2;
                int q   = idx & 3;
                int grow = rowBase + row;
                pf[r] = (grow < NN) ? Xh4[(size_t)grow * 16 + cq + q]
                                    : make_uint4(0, 0, 0, 0);
            }
        }

#pragma unroll
        for (int s = 0; s < 2; s++) {
            int kl = s * 8;
            uint32_t a00, a01, a02, a03, a10, a11, a12, a13;
            if (c < 4) {
                int ko = c * 16 + kl + ak;
                a00 = sAgg[arG + ko];
                a01 = sAgg[arG + 8 * AGS + ko];
                a02 = sAgg[arG + ko + 4];
                a03 = sAgg[arG + 8 * AGS + ko + 4];
                a10 = sAgg[arG + 16 * AGS + ko];
                a11 = sAgg[arG + 24 * AGS + ko];
                a12 = sAgg[arG + 16 * AGS + ko + 4];
                a13 = sAgg[arG + 24 * AGS + ko + 4];
            } else {
                int ko = kl + ak;
                a00 = sX[arX + ko];
                a01 = sX[arX + 8 * AS2 + ko];
                a02 = sX[arX + ko + 4];
                a03 = sX[arX + 8 * AS2 + ko + 4];
                a10 = sX[arX + 16 * AS2 + ko];
                a11 = sX[arX + 24 * AS2 + ko];
                a12 = sX[arX + 16 * AS2 + ko + 4];
                a13 = sX[arX + 24 * AS2 + ko + 4];
            }
            int kg2 = c * 16 + kl;
            const uint32_t* bp = &sW[(kg2 + ak) * WS2 + wn + g8];
            uint32_t b0[8], b1[8];
#pragma unroll
            for (int j = 0; j < 8; j++) {
                b0[j] = bp[j * 8];
                b1[j] = bp[j * 8 + 4 * WS2];
            }
#pragma unroll
            for (int j = 0; j < 8; j++)
                mma_f16(acc[0][j], a00, a01, a02, a03, b0[j], b1[j]);
#pragma unroll
            for (int j = 0; j < 8; j++)
                mma_f16(acc[1][j], a10, a11, a12, a13, b0[j], b1[j]);
        }

        if (c >= 3 && c < 7) {
            __syncthreads();     // readers of sX chunk c done
#pragma unroll
            for (int r = 0; r < 2; r++) {
                int idx = tid + r * 256;
                int row = idx >> 2;
                int q   = idx & 3;
                uint32_t* d = &sX[row * AS2 + q * 4];
                d[0] = pf[r].x; d[1] = pf[r].y; d[2] = pf[r].z; d[3] = pf[r].w;
            }
            __syncthreads();     // chunk c+1 visible
        }
    }

    // ---- Epilogue: bias (+relu); fp16 and/or fp32 stores ----
    const int coff = ak * 2;
    const int rbase = rowBase + wm + g8;
#pragma unroll
    for (int t = 0; t < 2; t++) {
        int ra = rbase + t * 16;
        int rb = ra + 8;
#pragma unroll
        for (int j = 0; j < 8; j++) {
            int col = wn + j * 8 + coff;
            float2 bb = *(const float2*)&bias[col];
            float2 o0, o1;
            o0.x = acc[t][j][0] + bb.x; o0.y = acc[t][j][1] + bb.y;
            o1.x = acc[t][j][2] + bb.x; o1.y = acc[t][j][3] + bb.y;
            if (do_relu) {
                o0.x = fmaxf(o0.x, 0.f); o0.y = fmaxf(o0.y, 0.f);
                o1.x = fmaxf(o1.x, 0.f); o1.y = fmaxf(o1.y, 0.f);
            }
            if (ra < NN) {
                if (out16)
                    *(__half2*)&out16[(size_t)ra * 64 + (col >> 1)]
                        = __floats2half2_rn(o0.x, o0.y);
                if (out32) *(float2*)&out32[(size_t)ra * FC + col] = o0;
            }
            if (rb < NN) {
                if (out16)
                    *(__half2*)&out16[(size_t)rb * 64 + (col >> 1)]
                        = __floats2half2_rn(o1.x, o1.y);
                if (out32) *(float2*)&out32[(size_t)rb * FC + col] = o1;
            }
        }
    }
}

// ---------------------------------------------------------------------------
// Fused mean-pool + classifier (batch sorted -> contiguous per-graph ranges)
// ---------------------------------------------------------------------------
__global__ void poolfinal_kernel(const float* __restrict__ h,
                                 const void* __restrict__ batch,
                                 const float* __restrict__ Wlin,
                                 const float* __restrict__ blin,
                                 float* __restrict__ out)
{
    __shared__ float sp[FC];
    __shared__ int bounds[2];
    int g = blockIdx.x;
    int t = threadIdx.x;
    int is64 = g_is64;

    if (t < 2) {
        long long target = g + t;
        int lo = 0, hi = NN;
        while (lo < hi) {
            int mid = (lo + hi) >> 1;
            if (load_idx(batch, mid, is64) < target) lo = mid + 1;
            else hi = mid;
        }
        bounds[t] = lo;
    }
    __syncthreads();
    int lo = bounds[0], hi = bounds[1];

    float s = 0.f;
    for (int n = lo; n < hi; n++)
        s += h[(size_t)n * FC + t];
    float inv = 1.0f / fmaxf((float)(hi - lo), 1.0f);
    sp[t] = s * inv;
    __syncthreads();

    if (t < NOUT) {
        float acc = blin[t];
#pragma unroll 16
        for (int k = 0; k < FC; k++)
            acc += sp[k] * Wlin[k * NOUT + t];
        out[g * NOUT + t] = acc;
    }
}

// ---------------------------------------------------------------------------
extern "C" void kernel_launch(void* const* d_in, const int* in_sizes, int n_in,
                              void* d_out, int out_size)
{
    const float* x     = (const float*)d_in[0];
    const void*  ei    = d_in[1];
    const void*  batch = d_in[2];
    const float* W1r = (const float*)d_in[3];
    const float* b1  = (const float*)d_in[4];
    const float* W1s = (const float*)d_in[5];
    const float* W2r = (const float*)d_in[6];
    const float* b2  = (const float*)d_in[7];
    const float* W2s = (const float*)d_in[8];
    const float* W3r = (const float*)d_in[9];
    const float* b3  = (const float*)d_in[10];
    const float* W3s = (const float*)d_in[11];
    const float* Wl  = (const float*)d_in[12];
    const float* bl  = (const float*)d_in[13];
    float* out = (float*)d_out;

    cudaFuncSetAttribute(gconv_fused_kernel,
                         cudaFuncAttributeMaxDynamicSharedMemorySize,
                         GC_SMEM_BYTES);

    uint2 *f16a, *f16b;
    float4 *ha;
    int *rowptr, *cursor, *esrc, *part;
    cudaGetSymbolAddress((void**)&f16a,   g_f16a);
    cudaGetSymbolAddress((void**)&f16b,   g_f16b);
    cudaGetSymbolAddress((void**)&ha,     g_ha);
    cudaGetSymbolAddress((void**)&rowptr, g_rowptr);
    cudaGetSymbolAddress((void**)&cursor, g_cursor);
    cudaGetSymbolAddress((void**)&esrc,   g_esrc);
    cudaGetSymbolAddress((void**)&part,   g_part);

    const int gblocks = (NN + 127) / 128;
    const int cblocks = (NN * 32 + 255) / 256;

    detect_kernel<<<1, 512>>>((const long long*)ei);

    // ---- CSR build ----
    cudaMemsetAsync(rowptr, 0, NSCAN * sizeof(int));
    hist_kernel<<<2048, 256>>>(ei, rowptr);
    scanA_kernel<<<NBLK, SCAN_BLK>>>(rowptr, part);
    scanC_kernel<<<NBLK, SCAN_BLK>>>(rowptr, part, cursor);
    fill_kernel<<<2048, 256>>>(ei, cursor, esrc);

    // fp16 copy of x
    cvt16_kernel<<<cblocks, 256>>>((const float4*)x, f16a);

    // Layer 1: f16a -> f16b
    gconv_fused_kernel<<<gblocks, 256, GC_SMEM_BYTES>>>(
        f16a, rowptr, esrc, W1r, W1s, b1, (float*)0, (uint32_t*)f16b, 1);
    // Layer 2: f16b -> f16a
    gconv_fused_kernel<<<gblocks, 256, GC_SMEM_BYTES>>>(
        f16b, rowptr, esrc, W2r, W2s, b2, (float*)0, (uint32_t*)f16a, 1);
    // Layer 3: f16a -> fp32 ha (no relu)
    gconv_fused_kernel<<<gblocks, 256, GC_SMEM_BYTES>>>(
        f16a, rowptr, esrc, W3r, W3s, b3, (float*)ha, (uint32_t*)0, 0);

    // Fused mean-pool + classifier
    poolfinal_kernel<<<NG, FC>>>((const float*)ha, batch, Wl, bl, out);
}

// round 12
// speedup vs baseline: 1.2565x; 1.2565x over previous
#include <cuda_runtime.h>
#include <cuda_fp16.h>
#include <cstdint>

#define NN   100000
#define FC   128
#define NE   1600000
#define NG   512
#define NOUT 10
#define NSCAN (NN + 1)
#define SCAN_BLK 1024
#define NBLK ((NSCAN + SCAN_BLK - 1) / SCAN_BLK)   // 98

// Scratch (device globals)
__device__ uint2  g_agg16[(size_t)NN * 32];   // fp16 aggregate  [NN][64 words]
__device__ uint2  g_f16a [(size_t)NN * 32];   // fp16 features ping
__device__ uint2  g_f16b [(size_t)NN * 32];   // fp16 features pong
__device__ float4 g_ha   [(size_t)NN * (FC / 4)];   // fp32 layer-3 output
__device__ int    g_rowptr[NSCAN];
__device__ int    g_cursor[NN];
__device__ int    g_esrc[NE];
__device__ int    g_part[NBLK];
__device__ int    g_is64;

// ---------------------------------------------------------------------------
// Index dtype detection (int32 vs int64 edge/batch buffers)
// ---------------------------------------------------------------------------
__global__ void detect_kernel(const long long* __restrict__ ei)
{
    __shared__ int ok;
    if (threadIdx.x == 0) ok = 1;
    __syncthreads();
    long long v = ei[threadIdx.x];           // 512 threads
    if (v < 0 || v >= NN) atomicAnd(&ok, 0);
    __syncthreads();
    if (threadIdx.x == 0) g_is64 = ok;
}

__device__ __forceinline__ long long load_idx(const void* base, int i, int is64)
{
    if (is64) return ((const long long*)base)[i];
    return (long long)((const int*)base)[i];
}

// ---------------------------------------------------------------------------
// CSR build: histogram -> scan -> fill
// ---------------------------------------------------------------------------
__global__ void hist_kernel(const void* __restrict__ ei, int* __restrict__ deg)
{
    int is64 = g_is64;
    for (int e = blockIdx.x * blockDim.x + threadIdx.x; e < NE;
         e += gridDim.x * blockDim.x) {
        int d = (int)load_idx(ei, e + NE, is64);
        atomicAdd(&deg[d + 1], 1);
    }
}

__global__ void scanA_kernel(int* __restrict__ deg, int* __restrict__ part)
{
    __shared__ int sm[SCAN_BLK];
    int tid = threadIdx.x;
    int i = blockIdx.x * SCAN_BLK + tid;
    int v = (i < NSCAN) ? deg[i] : 0;
    sm[tid] = v;
    __syncthreads();
#pragma unroll
    for (int off = 1; off < SCAN_BLK; off <<= 1) {
        int t = (tid >= off) ? sm[tid - off] : 0;
        __syncthreads();
        sm[tid] += t;
        __syncthreads();
    }
    if (i < NSCAN) deg[i] = sm[tid];
    if (tid == SCAN_BLK - 1) part[blockIdx.x] = sm[tid];
}

// scanC folds the cross-block partial prefix (98 partials) in-kernel.
__global__ void scanC_kernel(int* __restrict__ deg, const int* __restrict__ part,
                             int* __restrict__ cursor)
{
    __shared__ int soff;
    if (threadIdx.x == 0) soff = 0;
    __syncthreads();
    if (threadIdx.x < blockIdx.x)          // blockIdx.x <= 97 < blockDim
        atomicAdd(&soff, part[threadIdx.x]);
    __syncthreads();
    int i = blockIdx.x * SCAN_BLK + threadIdx.x;
    if (i < NSCAN) {
        int v = deg[i] + soff;
        deg[i] = v;
        if (i < NN) cursor[i] = v;
    }
}

__global__ void fill_kernel(const void* __restrict__ ei,
                            int* __restrict__ cursor, int* __restrict__ esrc)
{
    int is64 = g_is64;
    for (int e = blockIdx.x * blockDim.x + threadIdx.x; e < NE;
         e += gridDim.x * blockDim.x) {
        int s = (int)load_idx(ei, e, is64);
        int d = (int)load_idx(ei, e + NE, is64);
        int pos = atomicAdd(&cursor[d], 1);
        esrc[pos] = s;
    }
}

// ---------------------------------------------------------------------------
// fp32 -> fp16 convert
// ---------------------------------------------------------------------------
__global__ void cvt16_kernel(const float4* __restrict__ src, uint2* __restrict__ dst)
{
    int i = blockIdx.x * blockDim.x + threadIdx.x;
    if (i >= NN * 32) return;
    float4 v = src[i];
    uint2 o;
    *(__half2*)&o.x = __floats2half2_rn(v.x, v.y);
    *(__half2*)&o.y = __floats2half2_rn(v.z, v.w);
    dst[i] = o;
}

// ---------------------------------------------------------------------------
// Atomic-free fp16 gather: agg16[n] = sum_{j in row n} xh[esrc[j]]
// fp32 accumulation, fp16 output. One warp per node; unroll 4 for MLP.
// ---------------------------------------------------------------------------
__global__ void gather_h_kernel(const uint2* __restrict__ xh,
                                const int* __restrict__ rowptr,
                                const int* __restrict__ esrc,
                                uint2* __restrict__ agg16)
{
    int n = blockIdx.x * 8 + (threadIdx.x >> 5);
    if (n >= NN) return;
    int c = threadIdx.x & 31;
    int lo = __ldg(&rowptr[n]);
    int hi = __ldg(&rowptr[n + 1]);
    float4 a0 = make_float4(0.f, 0.f, 0.f, 0.f);
    float4 a1 = make_float4(0.f, 0.f, 0.f, 0.f);
    float4 a2 = make_float4(0.f, 0.f, 0.f, 0.f);
    float4 a3 = make_float4(0.f, 0.f, 0.f, 0.f);
    int j = lo;
    for (; j + 4 <= hi; j += 4) {
        int s0 = __ldg(&esrc[j]);
        int s1 = __ldg(&esrc[j + 1]);
        int s2 = __ldg(&esrc[j + 2]);
        int s3 = __ldg(&esrc[j + 3]);
        uint2 v0 = xh[(size_t)s0 * 32 + c];
        uint2 v1 = xh[(size_t)s1 * 32 + c];
        uint2 v2 = xh[(size_t)s2 * 32 + c];
        uint2 v3 = xh[(size_t)s3 * 32 + c];
        float2 p0 = __half22float2(*(__half2*)&v0.x);
        float2 p1 = __half22float2(*(__half2*)&v0.y);
        a0.x += p0.x; a0.y += p0.y; a0.z += p1.x; a0.w += p1.y;
        float2 q0 = __half22float2(*(__half2*)&v1.x);
        float2 q1 = __half22float2(*(__half2*)&v1.y);
        a1.x += q0.x; a1.y += q0.y; a1.z += q1.x; a1.w += q1.y;
        float2 r0 = __half22float2(*(__half2*)&v2.x);
        float2 r1 = __half22float2(*(__half2*)&v2.y);
        a2.x += r0.x; a2.y += r0.y; a2.z += r1.x; a2.w += r1.y;
        float2 t0 = __half22float2(*(__half2*)&v3.x);
        float2 t1 = __half22float2(*(__half2*)&v3.y);
        a3.x += t0.x; a3.y += t0.y; a3.z += t1.x; a3.w += t1.y;
    }
    for (; j < hi; j++) {
        int s0 = __ldg(&esrc[j]);
        uint2 v0 = xh[(size_t)s0 * 32 + c];
        float2 p0 = __half22float2(*(__half2*)&v0.x);
        float2 p1 = __half22float2(*(__half2*)&v0.y);
        a0.x += p0.x; a0.y += p0.y; a0.z += p1.x; a0.w += p1.y;
    }
    a0.x += a1.x; a0.y += a1.y; a0.z += a1.z; a0.w += a1.w;
    a2.x += a3.x; a2.y += a3.y; a2.z += a3.z; a2.w += a3.w;
    a0.x += a2.x; a0.y += a2.y; a0.z += a2.z; a0.w += a2.w;
    uint2 o;
    *(__half2*)&o.x = __floats2half2_rn(a0.x, a0.y);
    *(__half2*)&o.y = __floats2half2_rn(a0.z, a0.w);
    agg16[(size_t)n * 32 + c] = o;
}

// ---------------------------------------------------------------------------
// fp16 tensor-core GraphConv: out = (relu?)([A|X] @ [Wrel;Wroot] + b)
//   M=128/block, N=128, K=256, fp16 mma.m16n8k16, fp32 accumulate.
//   2 blocks/SM (80KB smem). Emits fp16 and/or fp32 outputs.
// ---------------------------------------------------------------------------
#define WS2 136
#define AS2 20
#define SWH_WORDS (128 * WS2)    // 17408
#define SAH_WORDS (128 * AS2)    //  2560
#define GC_SMEM_BYTES ((SWH_WORDS + SAH_WORDS) * 4)

__device__ __forceinline__ void mma_f16(float c[4],
                                        uint32_t a0, uint32_t a1,
                                        uint32_t a2, uint32_t a3,
                                        uint32_t b0, uint32_t b1)
{
    asm volatile("mma.sync.aligned.m16n8k16.row.col.f32.f16.f16.f32 "
                 "{%0,%1,%2,%3}, {%4,%5,%6,%7}, {%8,%9}, {%0,%1,%2,%3};"
                 : "+f"(c[0]), "+f"(c[1]), "+f"(c[2]), "+f"(c[3])
                 : "r"(a0), "r"(a1), "r"(a2), "r"(a3), "r"(b0), "r"(b1));
}

__global__ __launch_bounds__(256, 2) void gconv_h_kernel(
    const uint4* __restrict__ Ah, const uint4* __restrict__ Xh,
    const float* __restrict__ Wrel, const float* __restrict__ Wroot,
    const float* __restrict__ bias, float* __restrict__ out32,
    uint32_t* __restrict__ out16, int do_relu)
{
    extern __shared__ uint32_t smw[];
    uint32_t* sW = smw;               // [k2 0..127][n 0..127] stride 136
    uint32_t* sA = smw + SWH_WORDS;   // [row 0..127][k2 0..15] stride 20

    const int tid  = threadIdx.x;
    const int warp = tid >> 5;
    const int lane = tid & 31;
    const int rowBase = blockIdx.x * 128;

    const int wm = (warp & 3) * 32;   // warp rows [wm, wm+32)
    const int wn = (warp >> 2) * 64;  // warp cols [wn, wn+64)
    const int g8 = lane >> 2;
    const int ak = lane & 3;

    // ---- Stage stacked weights as half2(k even, k odd) ----
    for (int i = tid; i < 4096; i += 256) {
        int k2 = i >> 5;          // 0..127
        int n4 = i & 31;
        const float* r0 = (k2 < 64) ? &Wrel[(2 * k2) * FC + n4 * 4]
                                    : &Wroot[(2 * k2 - 128) * FC + n4 * 4];
        float4 w0 = *(const float4*)r0;
        float4 w1 = *(const float4*)(r0 + FC);
        uint32_t* d = &sW[k2 * WS2 + n4 * 4];
        *(__half2*)&d[0] = __floats2half2_rn(w0.x, w1.x);
        *(__half2*)&d[1] = __floats2half2_rn(w0.y, w1.y);
        *(__half2*)&d[2] = __floats2half2_rn(w0.z, w1.z);
        *(__half2*)&d[3] = __floats2half2_rn(w0.w, w1.w);
    }

    // ---- Stage chunk 0 (k [0,32) of agg) ----
#pragma unroll
    for (int r = 0; r < 2; r++) {
        int idx = tid + r * 256;
        int row = idx >> 2;
        int q   = idx & 3;
        int grow = rowBase + row;
        uint4 v = make_uint4(0, 0, 0, 0);
        if (grow < NN) v = Ah[(size_t)grow * 16 + q];
        uint32_t* d = &sA[row * AS2 + q * 4];
        d[0] = v.x; d[1] = v.y; d[2] = v.z; d[3] = v.w;
    }
    __syncthreads();

    float acc[2][8][4];
#pragma unroll
    for (int t = 0; t < 2; t++)
#pragma unroll
        for (int j = 0; j < 8; j++)
#pragma unroll
            for (int q = 0; q < 4; q++) acc[t][j][q] = 0.f;

    const int ar = (wm + g8) * AS2;

    uint4 pf[2];
#pragma unroll 1
    for (int c = 0; c < 8; c++) {
        if (c < 7) {
            const uint4* src = (c + 1 < 4) ? Ah : Xh;
            int cq = ((c + 1) & 3) * 4;
#pragma unroll
            for (int r = 0; r < 2; r++) {
                int idx = tid + r * 256;
                int row = idx >> 2;
                int q   = idx & 3;
                int grow = rowBase + row;
                pf[r] = (grow < NN) ? src[(size_t)grow * 16 + cq + q]
                                    : make_uint4(0, 0, 0, 0);
            }
        }

#pragma unroll
        for (int s = 0; s < 2; s++) {
            int kl = s * 8;
            uint32_t a00 = sA[ar + kl + ak];
            uint32_t a01 = sA[ar + 8 * AS2 + kl + ak];
            uint32_t a02 = sA[ar + kl + ak + 4];
            uint32_t a03 = sA[ar + 8 * AS2 + kl + ak + 4];
            uint32_t a10 = sA[ar + 16 * AS2 + kl + ak];
            uint32_t a11 = sA[ar + 24 * AS2 + kl + ak];
            uint32_t a12 = sA[ar + 16 * AS2 + kl + ak + 4];
            uint32_t a13 = sA[ar + 24 * AS2 + kl + ak + 4];
            int kg2 = c * 16 + kl;
            const uint32_t* bp = &sW[(kg2 + ak) * WS2 + wn + g8];
            uint32_t b0[8], b1[8];
#pragma unroll
            for (int j = 0; j < 8; j++) {
                b0[j] = bp[j * 8];
                b1[j] = bp[j * 8 + 4 * WS2];
            }
#pragma unroll
            for (int j = 0; j < 8; j++)
                mma_f16(acc[0][j], a00, a01, a02, a03, b0[j], b1[j]);
#pragma unroll
            for (int j = 0; j < 8; j++)
                mma_f16(acc[1][j], a10, a11, a12, a13, b0[j], b1[j]);
        }
        __syncthreads();

        if (c < 7) {
#pragma unroll
            for (int r = 0; r < 2; r++) {
                int idx = tid + r * 256;
                int row = idx >> 2;
                int q   = idx & 3;
                uint32_t* d = &sA[row * AS2 + q * 4];
                d[0] = pf[r].x; d[1] = pf[r].y; d[2] = pf[r].z; d[3] = pf[r].w;
            }
            __syncthreads();
        }
    }

    // ---- Epilogue: bias (+relu); fp16 and/or fp32 stores ----
    const int coff = ak * 2;
    const int rbase = rowBase + wm + g8;
#pragma unroll
    for (int t = 0; t < 2; t++) {
        int ra = rbase + t * 16;
        int rb = ra + 8;
#pragma unroll
        for (int j = 0; j < 8; j++) {
            int col = wn + j * 8 + coff;
            float2 bb = *(const float2*)&bias[col];
            float2 o0, o1;
            o0.x = acc[t][j][0] + bb.x; o0.y = acc[t][j][1] + bb.y;
            o1.x = acc[t][j][2] + bb.x; o1.y = acc[t][j][3] + bb.y;
            if (do_relu) {
                o0.x = fmaxf(o0.x, 0.f); o0.y = fmaxf(o0.y, 0.f);
                o1.x = fmaxf(o1.x, 0.f); o1.y = fmaxf(o1.y, 0.f);
            }
            if (ra < NN) {
                if (out16)
                    *(__half2*)&out16[(size_t)ra * 64 + (col >> 1)]
                        = __floats2half2_rn(o0.x, o0.y);
                if (out32) *(float2*)&out32[(size_t)ra * FC + col] = o0;
            }
            if (rb < NN) {
                if (out16)
                    *(__half2*)&out16[(size_t)rb * 64 + (col >> 1)]
                        = __floats2half2_rn(o1.x, o1.y);
                if (out32) *(float2*)&out32[(size_t)rb * FC + col] = o1;
            }
        }
    }
}

// ---------------------------------------------------------------------------
// Fused mean-pool + classifier (batch sorted -> contiguous per-graph ranges)
// ---------------------------------------------------------------------------
__global__ void poolfinal_kernel(const float* __restrict__ h,
                                 const void* __restrict__ batch,
                                 const float* __restrict__ Wlin,
                                 const float* __restrict__ blin,
                                 float* __restrict__ out)
{
    __shared__ float sp[FC];
    __shared__ int bounds[2];
    int g = blockIdx.x;
    int t = threadIdx.x;
    int is64 = g_is64;

    if (t < 2) {
        long long target = g + t;
        int lo = 0, hi = NN;
        while (lo < hi) {
            int mid = (lo + hi) >> 1;
            if (load_idx(batch, mid, is64) < target) lo = mid + 1;
            else hi = mid;
        }
        bounds[t] = lo;
    }
    __syncthreads();
    int lo = bounds[0], hi = bounds[1];

    float s = 0.f;
    for (int n = lo; n < hi; n++)
        s += h[(size_t)n * FC + t];
    float inv = 1.0f / fmaxf((float)(hi - lo), 1.0f);
    sp[t] = s * inv;
    __syncthreads();

    if (t < NOUT) {
        float acc = blin[t];
#pragma unroll 16
        for (int k = 0; k < FC; k++)
            acc += sp[k] * Wlin[k * NOUT + t];
        out[g * NOUT + t] = acc;
    }
}

// ---------------------------------------------------------------------------
extern "C" void kernel_launch(void* const* d_in, const int* in_sizes, int n_in,
                              void* d_out, int out_size)
{
    const float* x     = (const float*)d_in[0];
    const void*  ei    = d_in[1];
    const void*  batch = d_in[2];
    const float* W1r = (const float*)d_in[3];
    const float* b1  = (const float*)d_in[4];
    const float* W1s = (const float*)d_in[5];
    const float* W2r = (const float*)d_in[6];
    const float* b2  = (const float*)d_in[7];
    const float* W2s = (const float*)d_in[8];
    const float* W3r = (const float*)d_in[9];
    const float* b3  = (const float*)d_in[10];
    const float* W3s = (const float*)d_in[11];
    const float* Wl  = (const float*)d_in[12];
    const float* bl  = (const float*)d_in[13];
    float* out = (float*)d_out;

    cudaFuncSetAttribute(gconv_h_kernel,
                         cudaFuncAttributeMaxDynamicSharedMemorySize,
                         GC_SMEM_BYTES);

    uint2 *agg16, *f16a, *f16b;
    float4 *ha;
    int *rowptr, *cursor, *esrc, *part;
    cudaGetSymbolAddress((void**)&agg16,  g_agg16);
    cudaGetSymbolAddress((void**)&f16a,   g_f16a);
    cudaGetSymbolAddress((void**)&f16b,   g_f16b);
    cudaGetSymbolAddress((void**)&ha,     g_ha);
    cudaGetSymbolAddress((void**)&rowptr, g_rowptr);
    cudaGetSymbolAddress((void**)&cursor, g_cursor);
    cudaGetSymbolAddress((void**)&esrc,   g_esrc);
    cudaGetSymbolAddress((void**)&part,   g_part);

    const int nblocks8 = (NN + 7) / 8;
    const int gblocks  = (NN + 127) / 128;
    const int cblocks  = (NN * 32 + 255) / 256;

    detect_kernel<<<1, 512>>>((const long long*)ei);

    // ---- CSR build ----
    cudaMemsetAsync(rowptr, 0, NSCAN * sizeof(int));
    hist_kernel<<<2048, 256>>>(ei, rowptr);
    scanA_kernel<<<NBLK, SCAN_BLK>>>(rowptr, part);
    scanC_kernel<<<NBLK, SCAN_BLK>>>(rowptr, part, cursor);
    fill_kernel<<<2048, 256>>>(ei, cursor, esrc);

    // fp16 copy of x
    cvt16_kernel<<<cblocks, 256>>>((const float4*)x, f16a);

    // Layer 1: f16a -> f16b
    gather_h_kernel<<<nblocks8, 256>>>(f16a, rowptr, esrc, agg16);
    gconv_h_kernel<<<gblocks, 256, GC_SMEM_BYTES>>>(
        (const uint4*)agg16, (const uint4*)f16a, W1r, W1s, b1,
        (float*)0, (uint32_t*)f16b, 1);
    // Layer 2: f16b -> f16a
    gather_h_kernel<<<nblocks8, 256>>>(f16b, rowptr, esrc, agg16);
    gconv_h_kernel<<<gblocks, 256, GC_SMEM_BYTES>>>(
        (const uint4*)agg16, (const uint4*)f16b, W2r, W2s, b2,
        (float*)0, (uint32_t*)f16a, 1);
    // Layer 3: f16a -> fp32 ha (no relu)
    gather_h_kernel<<<nblocks8, 256>>>(f16a, rowptr, esrc, agg16);
    gconv_h_kernel<<<gblocks, 256, GC_SMEM_BYTES>>>(
        (const uint4*)agg16, (const uint4*)f16a, W3r, W3s, b3,
        (float*)ha, (uint32_t*)0, 0);

    // Fused mean-pool + classifier
    poolfinal_kernel<<<NG, FC>>>((const float*)ha, batch, Wl, bl, out);
}

// round 13
// speedup vs baseline: 1.2690x; 1.0099x over previous
#include <cuda_runtime.h>
#include <cuda_fp16.h>
#include <cstdint>

#define NN   100000
#define FC   128
#define NE   1600000
#define NG   512
#define NOUT 10
#define NSCAN (NN + 1)
#define SCAN_BLK 1024
#define NBLK ((NSCAN + SCAN_BLK - 1) / SCAN_BLK)   // 98

// Scratch (device globals)
__device__ uint2  g_agg16[(size_t)NN * 32];   // fp16 aggregate  [NN][64 words]
__device__ uint2  g_f16a [(size_t)NN * 32];   // fp16 features ping
__device__ uint2  g_f16b [(size_t)NN * 32];   // fp16 features pong
__device__ float4 g_ha   [(size_t)NN * (FC / 4)];   // fp32 layer-3 output
__device__ int    g_rowptr[NSCAN];
__device__ int    g_cursor[NN];
__device__ int    g_esrc[NE];
__device__ int    g_part[NBLK];
__device__ int    g_is64;

// ---------------------------------------------------------------------------
// Index dtype detection (int32 vs int64 edge/batch buffers)
// ---------------------------------------------------------------------------
__global__ void detect_kernel(const long long* __restrict__ ei)
{
    __shared__ int ok;
    if (threadIdx.x == 0) ok = 1;
    __syncthreads();
    long long v = ei[threadIdx.x];           // 512 threads
    if (v < 0 || v >= NN) atomicAnd(&ok, 0);
    __syncthreads();
    if (threadIdx.x == 0) g_is64 = ok;
}

__device__ __forceinline__ long long load_idx(const void* base, int i, int is64)
{
    if (is64) return ((const long long*)base)[i];
    return (long long)((const int*)base)[i];
}

// ---------------------------------------------------------------------------
// CSR build: histogram -> scan -> fill
// ---------------------------------------------------------------------------
__global__ void hist_kernel(const void* __restrict__ ei, int* __restrict__ deg)
{
    int is64 = g_is64;
    for (int e = blockIdx.x * blockDim.x + threadIdx.x; e < NE;
         e += gridDim.x * blockDim.x) {
        int d = (int)load_idx(ei, e + NE, is64);
        atomicAdd(&deg[d + 1], 1);
    }
}

__global__ void scanA_kernel(int* __restrict__ deg, int* __restrict__ part)
{
    __shared__ int sm[SCAN_BLK];
    int tid = threadIdx.x;
    int i = blockIdx.x * SCAN_BLK + tid;
    int v = (i < NSCAN) ? deg[i] : 0;
    sm[tid] = v;
    __syncthreads();
#pragma unroll
    for (int off = 1; off < SCAN_BLK; off <<= 1) {
        int t = (tid >= off) ? sm[tid - off] : 0;
        __syncthreads();
        sm[tid] += t;
        __syncthreads();
    }
    if (i < NSCAN) deg[i] = sm[tid];
    if (tid == SCAN_BLK - 1) part[blockIdx.x] = sm[tid];
}

// scanC folds the cross-block partial prefix (98 partials) in-kernel.
__global__ void scanC_kernel(int* __restrict__ deg, const int* __restrict__ part,
                             int* __restrict__ cursor)
{
    __shared__ int soff;
    if (threadIdx.x == 0) soff = 0;
    __syncthreads();
    if (threadIdx.x < blockIdx.x)          // blockIdx.x <= 97 < blockDim
        atomicAdd(&soff, part[threadIdx.x]);
    __syncthreads();
    int i = blockIdx.x * SCAN_BLK + threadIdx.x;
    if (i < NSCAN) {
        int v = deg[i] + soff;
        deg[i] = v;
        if (i < NN) cursor[i] = v;
    }
}

__global__ void fill_kernel(const void* __restrict__ ei,
                            int* __restrict__ cursor, int* __restrict__ esrc)
{
    int is64 = g_is64;
    for (int e = blockIdx.x * blockDim.x + threadIdx.x; e < NE;
         e += gridDim.x * blockDim.x) {
        int s = (int)load_idx(ei, e, is64);
        int d = (int)load_idx(ei, e + NE, is64);
        int pos = atomicAdd(&cursor[d], 1);
        esrc[pos] = s;
    }
}

// ---------------------------------------------------------------------------
// fp32 -> fp16 convert
// ---------------------------------------------------------------------------
__global__ void cvt16_kernel(const float4* __restrict__ src, uint2* __restrict__ dst)
{
    int i = blockIdx.x * blockDim.x + threadIdx.x;
    if (i >= NN * 32) return;
    float4 v = src[i];
    uint2 o;
    *(__half2*)&o.x = __floats2half2_rn(v.x, v.y);
    *(__half2*)&o.y = __floats2half2_rn(v.z, v.w);
    dst[i] = o;
}

// ---------------------------------------------------------------------------
// Atomic-free fp16 gather, half-warp-row scheme:
//   Lanes 0-15 read edge j's full 256B row via uint4; lanes 16-31 read edge
//   j+1. Each lane accumulates 8 channels fp32; shfl_xor(16) merges halves.
//   agg16[n] = sum_{j in row n} xh[esrc[j]]
// ---------------------------------------------------------------------------
__device__ __forceinline__ void acc8(float a[8], uint4 v)
{
    float2 p0 = __half22float2(*(__half2*)&v.x);
    float2 p1 = __half22float2(*(__half2*)&v.y);
    float2 p2 = __half22float2(*(__half2*)&v.z);
    float2 p3 = __half22float2(*(__half2*)&v.w);
    a[0] += p0.x; a[1] += p0.y; a[2] += p1.x; a[3] += p1.y;
    a[4] += p2.x; a[5] += p2.y; a[6] += p3.x; a[7] += p3.y;
}

__global__ void gather_h_kernel(const uint4* __restrict__ xh4,
                                const int* __restrict__ rowptr,
                                const int* __restrict__ esrc,
                                uint4* __restrict__ agg16)
{
    int n = blockIdx.x * 8 + (threadIdx.x >> 5);
    if (n >= NN) return;
    int lane = threadIdx.x & 31;
    int half = lane >> 4;        // 0: even edges, 1: odd edges
    int qc   = lane & 15;        // uint4 slot within the 256B row

    int lo = __ldg(&rowptr[n]);
    int hi = __ldg(&rowptr[n + 1]);

    float a0[8] = {0.f, 0.f, 0.f, 0.f, 0.f, 0.f, 0.f, 0.f};
    float a1[8] = {0.f, 0.f, 0.f, 0.f, 0.f, 0.f, 0.f, 0.f};

    int j = lo;
    for (; j + 4 <= hi; j += 4) {           // 4 edges per iter, 2 rows in flight
        int s0 = __ldg(&esrc[j + half]);
        int s1 = __ldg(&esrc[j + 2 + half]);
        uint4 v0 = xh4[(size_t)s0 * 16 + qc];
        uint4 v1 = xh4[(size_t)s1 * 16 + qc];
        acc8(a0, v0);
        acc8(a1, v1);
    }
    for (; j < hi; j += 2) {                // predicated tail (0-3 edges)
        int jj = j + half;
        if (jj < hi) {
            int s = __ldg(&esrc[jj]);
            uint4 v = xh4[(size_t)s * 16 + qc];
            acc8(a0, v);
        }
    }

#pragma unroll
    for (int k = 0; k < 8; k++) {
        a0[k] += a1[k];
        a0[k] += __shfl_xor_sync(0xffffffffu, a0[k], 16);
    }

    if (half == 0) {
        uint4 o;
        *(__half2*)&o.x = __floats2half2_rn(a0[0], a0[1]);
        *(__half2*)&o.y = __floats2half2_rn(a0[2], a0[3]);
        *(__half2*)&o.z = __floats2half2_rn(a0[4], a0[5]);
        *(__half2*)&o.w = __floats2half2_rn(a0[6], a0[7]);
        agg16[(size_t)n * 16 + qc] = o;
    }
}

// ---------------------------------------------------------------------------
// fp16 tensor-core GraphConv: out = (relu?)([A|X] @ [Wrel;Wroot] + b)
//   M=128/block, N=128, K=256, fp16 mma.m16n8k16, fp32 accumulate.
//   2 blocks/SM (80KB smem). Emits fp16 and/or fp32 outputs.
// ---------------------------------------------------------------------------
#define WS2 136
#define AS2 20
#define SWH_WORDS (128 * WS2)    // 17408
#define SAH_WORDS (128 * AS2)    //  2560
#define GC_SMEM_BYTES ((SWH_WORDS + SAH_WORDS) * 4)

__device__ __forceinline__ void mma_f16(float c[4],
                                        uint32_t a0, uint32_t a1,
                                        uint32_t a2, uint32_t a3,
                                        uint32_t b0, uint32_t b1)
{
    asm volatile("mma.sync.aligned.m16n8k16.row.col.f32.f16.f16.f32 "
                 "{%0,%1,%2,%3}, {%4,%5,%6,%7}, {%8,%9}, {%0,%1,%2,%3};"
                 : "+f"(c[0]), "+f"(c[1]), "+f"(c[2]), "+f"(c[3])
                 : "r"(a0), "r"(a1), "r"(a2), "r"(a3), "r"(b0), "r"(b1));
}

__global__ __launch_bounds__(256, 2) void gconv_h_kernel(
    const uint4* __restrict__ Ah, const uint4* __restrict__ Xh,
    const float* __restrict__ Wrel, const float* __restrict__ Wroot,
    const float* __restrict__ bias, float* __restrict__ out32,
    uint32_t* __restrict__ out16, int do_relu)
{
    extern __shared__ uint32_t smw[];
    uint32_t* sW = smw;               // [k2 0..127][n 0..127] stride 136
    uint32_t* sA = smw + SWH_WORDS;   // [row 0..127][k2 0..15] stride 20

    const int tid  = threadIdx.x;
    const int warp = tid >> 5;
    const int lane = tid & 31;
    const int rowBase = blockIdx.x * 128;

    const int wm = (warp & 3) * 32;   // warp rows [wm, wm+32)
    const int wn = (warp >> 2) * 64;  // warp cols [wn, wn+64)
    const int g8 = lane >> 2;
    const int ak = lane & 3;

    // ---- Stage stacked weights as half2(k even, k odd) ----
    for (int i = tid; i < 4096; i += 256) {
        int k2 = i >> 5;          // 0..127
        int n4 = i & 31;
        const float* r0 = (k2 < 64) ? &Wrel[(2 * k2) * FC + n4 * 4]
                                    : &Wroot[(2 * k2 - 128) * FC + n4 * 4];
        float4 w0 = *(const float4*)r0;
        float4 w1 = *(const float4*)(r0 + FC);
        uint32_t* d = &sW[k2 * WS2 + n4 * 4];
        *(__half2*)&d[0] = __floats2half2_rn(w0.x, w1.x);
        *(__half2*)&d[1] = __floats2half2_rn(w0.y, w1.y);
        *(__half2*)&d[2] = __floats2half2_rn(w0.z, w1.z);
        *(__half2*)&d[3] = __floats2half2_rn(w0.w, w1.w);
    }

    // ---- Stage chunk 0 (k [0,32) of agg) ----
#pragma unroll
    for (int r = 0; r < 2; r++) {
        int idx = tid + r * 256;
        int row = idx >> 2;
        int q   = idx & 3;
        int grow = rowBase + row;
        uint4 v = make_uint4(0, 0, 0, 0);
        if (grow < NN) v = Ah[(size_t)grow * 16 + q];
        uint32_t* d = &sA[row * AS2 + q * 4];
        d[0] = v.x; d[1] = v.y; d[2] = v.z; d[3] = v.w;
    }
    __syncthreads();

    float acc[2][8][4];
#pragma unroll
    for (int t = 0; t < 2; t++)
#pragma unroll
        for (int j = 0; j < 8; j++)
#pragma unroll
            for (int q = 0; q < 4; q++) acc[t][j][q] = 0.f;

    const int ar = (wm + g8) * AS2;

    uint4 pf[2];
#pragma unroll 1
    for (int c = 0; c < 8; c++) {
        if (c < 7) {
            const uint4* src = (c + 1 < 4) ? Ah : Xh;
            int cq = ((c + 1) & 3) * 4;
#pragma unroll
            for (int r = 0; r < 2; r++) {
                int idx = tid + r * 256;
                int row = idx >> 2;
                int q   = idx & 3;
                int grow = rowBase + row;
                pf[r] = (grow < NN) ? src[(size_t)grow * 16 + cq + q]
                                    : make_uint4(0, 0, 0, 0);
            }
        }

#pragma unroll
        for (int s = 0; s < 2; s++) {
            int kl = s * 8;
            uint32_t a00 = sA[ar + kl + ak];
            uint32_t a01 = sA[ar + 8 * AS2 + kl + ak];
            uint32_t a02 = sA[ar + kl + ak + 4];
            uint32_t a03 = sA[ar + 8 * AS2 + kl + ak + 4];
            uint32_t a10 = sA[ar + 16 * AS2 + kl + ak];
            uint32_t a11 = sA[ar + 24 * AS2 + kl + ak];
            uint32_t a12 = sA[ar + 16 * AS2 + kl + ak + 4];
            uint32_t a13 = sA[ar + 24 * AS2 + kl + ak + 4];
            int kg2 = c * 16 + kl;
            const uint32_t* bp = &sW[(kg2 + ak) * WS2 + wn + g8];
            uint32_t b0[8], b1[8];
#pragma unroll
            for (int j = 0; j < 8; j++) {
                b0[j] = bp[j * 8];
                b1[j] = bp[j * 8 + 4 * WS2];
            }
#pragma unroll
            for (int j = 0; j < 8; j++)
                mma_f16(acc[0][j], a00, a01, a02, a03, b0[j], b1[j]);
#pragma unroll
            for (int j = 0; j < 8; j++)
                mma_f16(acc[1][j], a10, a11, a12, a13, b0[j], b1[j]);
        }
        __syncthreads();

        if (c < 7) {
#pragma unroll
            for (int r = 0; r < 2; r++) {
                int idx = tid + r * 256;
                int row = idx >> 2;
                int q   = idx & 3;
                uint32_t* d = &sA[row * AS2 + q * 4];
                d[0] = pf[r].x; d[1] = pf[r].y; d[2] = pf[r].z; d[3] = pf[r].w;
            }
            __syncthreads();
        }
    }

    // ---- Epilogue: bias (+relu); fp16 and/or fp32 stores ----
    const int coff = ak * 2;
    const int rbase = rowBase + wm + g8;
#pragma unroll
    for (int t = 0; t < 2; t++) {
        int ra = rbase + t * 16;
        int rb = ra + 8;
#pragma unroll
        for (int j = 0; j < 8; j++) {
            int col = wn + j * 8 + coff;
            float2 bb = *(const float2*)&bias[col];
            float2 o0, o1;
            o0.x = acc[t][j][0] + bb.x; o0.y = acc[t][j][1] + bb.y;
            o1.x = acc[t][j][2] + bb.x; o1.y = acc[t][j][3] + bb.y;
            if (do_relu) {
                o0.x = fmaxf(o0.x, 0.f); o0.y = fmaxf(o0.y, 0.f);
                o1.x = fmaxf(o1.x, 0.f); o1.y = fmaxf(o1.y, 0.f);
            }
            if (ra < NN) {
                if (out16)
                    *(__half2*)&out16[(size_t)ra * 64 + (col >> 1)]
                        = __floats2half2_rn(o0.x, o0.y);
                if (out32) *(float2*)&out32[(size_t)ra * FC + col] = o0;
            }
            if (rb < NN) {
                if (out16)
                    *(__half2*)&out16[(size_t)rb * 64 + (col >> 1)]
                        = __floats2half2_rn(o1.x, o1.y);
                if (out32) *(float2*)&out32[(size_t)rb * FC + col] = o1;
            }
        }
    }
}

// ---------------------------------------------------------------------------
// Fused mean-pool + classifier (batch sorted -> contiguous per-graph ranges)
// ---------------------------------------------------------------------------
__global__ void poolfinal_kernel(const float* __restrict__ h,
                                 const void* __restrict__ batch,
                                 const float* __restrict__ Wlin,
                                 const float* __restrict__ blin,
                                 float* __restrict__ out)
{
    __shared__ float sp[FC];
    __shared__ int bounds[2];
    int g = blockIdx.x;
    int t = threadIdx.x;
    int is64 = g_is64;

    if (t < 2) {
        long long target = g + t;
        int lo = 0, hi = NN;
        while (lo < hi) {
            int mid = (lo + hi) >> 1;
            if (load_idx(batch, mid, is64) < target) lo = mid + 1;
            else hi = mid;
        }
        bounds[t] = lo;
    }
    __syncthreads();
    int lo = bounds[0], hi = bounds[1];

    float s = 0.f;
    for (int n = lo; n < hi; n++)
        s += h[(size_t)n * FC + t];
    float inv = 1.0f / fmaxf((float)(hi - lo), 1.0f);
    sp[t] = s * inv;
    __syncthreads();

    if (t < NOUT) {
        float acc = blin[t];
#pragma unroll 16
        for (int k = 0; k < FC; k++)
            acc += sp[k] * Wlin[k * NOUT + t];
        out[g * NOUT + t] = acc;
    }
}

// ---------------------------------------------------------------------------
extern "C" void kernel_launch(void* const* d_in, const int* in_sizes, int n_in,
                              void* d_out, int out_size)
{
    const float* x     = (const float*)d_in[0];
    const void*  ei    = d_in[1];
    const void*  batch = d_in[2];
    const float* W1r = (const float*)d_in[3];
    const float* b1  = (const float*)d_in[4];
    const float* W1s = (const float*)d_in[5];
    const float* W2r = (const float*)d_in[6];
    const float* b2  = (const float*)d_in[7];
    const float* W2s = (const float*)d_in[8];
    const float* W3r = (const float*)d_in[9];
    const float* b3  = (const float*)d_in[10];
    const float* W3s = (const float*)d_in[11];
    const float* Wl  = (const float*)d_in[12];
    const float* bl  = (const float*)d_in[13];
    float* out = (float*)d_out;

    cudaFuncSetAttribute(gconv_h_kernel,
                         cudaFuncAttributeMaxDynamicSharedMemorySize,
                         GC_SMEM_BYTES);

    uint2 *agg16, *f16a, *f16b;
    float4 *ha;
    int *rowptr, *cursor, *esrc, *part;
    cudaGetSymbolAddress((void**)&agg16,  g_agg16);
    cudaGetSymbolAddress((void**)&f16a,   g_f16a);
    cudaGetSymbolAddress((void**)&f16b,   g_f16b);
    cudaGetSymbolAddress((void**)&ha,     g_ha);
    cudaGetSymbolAddress((void**)&rowptr, g_rowptr);
    cudaGetSymbolAddress((void**)&cursor, g_cursor);
    cudaGetSymbolAddress((void**)&esrc,   g_esrc);
    cudaGetSymbolAddress((void**)&part,   g_part);

    const int nblocks8 = (NN + 7) / 8;
    const int gblocks  = (NN + 127) / 128;
    const int cblocks  = (NN * 32 + 255) / 256;

    detect_kernel<<<1, 512>>>((const long long*)ei);

    // ---- CSR build ----
    cudaMemsetAsync(rowptr, 0, NSCAN * sizeof(int));
    hist_kernel<<<2048, 256>>>(ei, rowptr);
    scanA_kernel<<<NBLK, SCAN_BLK>>>(rowptr, part);
    scanC_kernel<<<NBLK, SCAN_BLK>>>(rowptr, part, cursor);
    fill_kernel<<<2048, 256>>>(ei, cursor, esrc);

    // fp16 copy of x
    cvt16_kernel<<<cblocks, 256>>>((const float4*)x, f16a);

    // Layer 1: f16a -> f16b
    gather_h_kernel<<<nblocks8, 256>>>((const uint4*)f16a, rowptr, esrc,
                                       (uint4*)agg16);
    gconv_h_kernel<<<gblocks, 256, GC_SMEM_BYTES>>>(
        (const uint4*)agg16, (const uint4*)f16a, W1r, W1s, b1,
        (float*)0, (uint32_t*)f16b, 1);
    // Layer 2: f16b -> f16a
    gather_h_kernel<<<nblocks8, 256>>>((const uint4*)f16b, rowptr, esrc,
                                       (uint4*)agg16);
    gconv_h_kernel<<<gblocks, 256, GC_SMEM_BYTES>>>(
        (const uint4*)agg16, (const uint4*)f16b, W2r, W2s, b2,
        (float*)0, (uint32_t*)f16a, 1);
    // Layer 3: f16a -> fp32 ha (no relu)
    gather_h_kernel<<<nblocks8, 256>>>((const uint4*)f16a, rowptr, esrc,
                                       (uint4*)agg16);
    gconv_h_kernel<<<gblocks, 256, GC_SMEM_BYTES>>>(
        (const uint4*)agg16, (const uint4*)f16a, W3r, W3s, b3,
        (float*)ha, (uint32_t*)0, 0);

    // Fused mean-pool + classifier
    poolfinal_kernel<<<NG, FC>>>((const float*)ha, batch, Wl, bl, out);
}

// round 15
// speedup vs baseline: 1.3897x; 1.0951x over previous
#include <cuda_runtime.h>
#include <cuda_fp16.h>
#include <cstdint>

#define NN   100000
#define FC   128
#define NE   1600000
#define NG   512
#define NOUT 10
#define NSCAN (NN + 1)
#define SCAN_BLK 1024
#define NBLK ((NSCAN + SCAN_BLK - 1) / SCAN_BLK)   // 98

// Scratch (device globals)
__device__ uint2  g_agg16[(size_t)NN * 32];   // fp16 aggregate  [NN][64 words]
__device__ uint2  g_f16a [(size_t)NN * 32];   // fp16 features ping
__device__ uint2  g_f16b [(size_t)NN * 32];   // fp16 features pong
__device__ int    g_rowptr[NSCAN];
__device__ int    g_cursor[NN];
__device__ int    g_esrc[NE];
__device__ int    g_part[NBLK];
__device__ int    g_is64;

// ---------------------------------------------------------------------------
// Index dtype detection (int32 vs int64 edge/batch buffers)
// ---------------------------------------------------------------------------
__global__ void detect_kernel(const long long* __restrict__ ei)
{
    __shared__ int ok;
    if (threadIdx.x == 0) ok = 1;
    __syncthreads();
    long long v = ei[threadIdx.x];           // 512 threads
    if (v < 0 || v >= NN) atomicAnd(&ok, 0);
    __syncthreads();
    if (threadIdx.x == 0) g_is64 = ok;
}

__device__ __forceinline__ long long load_idx(const void* base, int i, int is64)
{
    if (is64) return ((const long long*)base)[i];
    return (long long)((const int*)base)[i];
}

// ---------------------------------------------------------------------------
// CSR build: histogram -> scan -> fill
// ---------------------------------------------------------------------------
__global__ void hist_kernel(const void* __restrict__ ei, int* __restrict__ deg)
{
    int is64 = g_is64;
    for (int e = blockIdx.x * blockDim.x + threadIdx.x; e < NE;
         e += gridDim.x * blockDim.x) {
        int d = (int)load_idx(ei, e + NE, is64);
        atomicAdd(&deg[d + 1], 1);
    }
}

__global__ void scanA_kernel(int* __restrict__ deg, int* __restrict__ part)
{
    __shared__ int sm[SCAN_BLK];
    int tid = threadIdx.x;
    int i = blockIdx.x * SCAN_BLK + tid;
    int v = (i < NSCAN) ? deg[i] : 0;
    sm[tid] = v;
    __syncthreads();
#pragma unroll
    for (int off = 1; off < SCAN_BLK; off <<= 1) {
        int t = (tid >= off) ? sm[tid - off] : 0;
        __syncthreads();
        sm[tid] += t;
        __syncthreads();
    }
    if (i < NSCAN) deg[i] = sm[tid];
    if (tid == SCAN_BLK - 1) part[blockIdx.x] = sm[tid];
}

// scanC folds the cross-block partial prefix (98 partials) in-kernel.
__global__ void scanC_kernel(int* __restrict__ deg, const int* __restrict__ part,
                             int* __restrict__ cursor)
{
    __shared__ int soff;
    if (threadIdx.x == 0) soff = 0;
    __syncthreads();
    if (threadIdx.x < blockIdx.x)          // blockIdx.x <= 97 < blockDim
        atomicAdd(&soff, part[threadIdx.x]);
    __syncthreads();
    int i = blockIdx.x * SCAN_BLK + threadIdx.x;
    if (i < NSCAN) {
        int v = deg[i] + soff;
        deg[i] = v;
        if (i < NN) cursor[i] = v;
    }
}

__global__ void fill_kernel(const void* __restrict__ ei,
                            int* __restrict__ cursor, int* __restrict__ esrc)
{
    int is64 = g_is64;
    for (int e = blockIdx.x * blockDim.x + threadIdx.x; e < NE;
         e += gridDim.x * blockDim.x) {
        int s = (int)load_idx(ei, e, is64);
        int d = (int)load_idx(ei, e + NE, is64);
        int pos = atomicAdd(&cursor[d], 1);
        esrc[pos] = s;
    }
}

// ---------------------------------------------------------------------------
// fp32 -> fp16 convert
// ---------------------------------------------------------------------------
__global__ void cvt16_kernel(const float4* __restrict__ src, uint2* __restrict__ dst)
{
    int i = blockIdx.x * blockDim.x + threadIdx.x;
    if (i >= NN * 32) return;
    float4 v = src[i];
    uint2 o;
    *(__half2*)&o.x = __floats2half2_rn(v.x, v.y);
    *(__half2*)&o.y = __floats2half2_rn(v.z, v.w);
    dst[i] = o;
}

// ---------------------------------------------------------------------------
// Atomic-free fp16 gather (R10 scheme): agg16[n] = sum_{j in row n} xh[esrc[j]]
// fp32 accumulation, fp16 output. One warp per node; unroll 2 dual accum.
// ---------------------------------------------------------------------------
__global__ void gather_h_kernel(const uint2* __restrict__ xh,
                                const int* __restrict__ rowptr,
                                const int* __restrict__ esrc,
                                uint2* __restrict__ agg16)
{
    int n = blockIdx.x * 8 + (threadIdx.x >> 5);
    if (n >= NN) return;
    int c = threadIdx.x & 31;
    int lo = __ldg(&rowptr[n]);
    int hi = __ldg(&rowptr[n + 1]);
    float4 a0 = make_float4(0.f, 0.f, 0.f, 0.f);
    float4 a1 = make_float4(0.f, 0.f, 0.f, 0.f);
    int j = lo;
    for (; j + 1 < hi; j += 2) {
        int s0 = __ldg(&esrc[j]);
        int s1 = __ldg(&esrc[j + 1]);
        uint2 v0 = xh[(size_t)s0 * 32 + c];
        uint2 v1 = xh[(size_t)s1 * 32 + c];
        float2 p0 = __half22float2(*(__half2*)&v0.x);
        float2 p1 = __half22float2(*(__half2*)&v0.y);
        float2 q0 = __half22float2(*(__half2*)&v1.x);
        float2 q1 = __half22float2(*(__half2*)&v1.y);
        a0.x += p0.x; a0.y += p0.y; a0.z += p1.x; a0.w += p1.y;
        a1.x += q0.x; a1.y += q0.y; a1.z += q1.x; a1.w += q1.y;
    }
    if (j < hi) {
        int s0 = __ldg(&esrc[j]);
        uint2 v0 = xh[(size_t)s0 * 32 + c];
        float2 p0 = __half22float2(*(__half2*)&v0.x);
        float2 p1 = __half22float2(*(__half2*)&v0.y);
        a0.x += p0.x; a0.y += p0.y; a0.z += p1.x; a0.w += p1.y;
    }
    uint2 o;
    *(__half2*)&o.x = __floats2half2_rn(a0.x + a1.x, a0.y + a1.y);
    *(__half2*)&o.y = __floats2half2_rn(a0.z + a1.z, a0.w + a1.w);
    agg16[(size_t)n * 32 + c] = o;
}

// ---------------------------------------------------------------------------
// fp16 tensor-core GraphConv: out = (relu?)([A|X] @ [Wrel;Wroot] + b)
//   M=128/block, N=128, K=256, fp16 mma.m16n8k16, fp32 accumulate.
//   2 blocks/SM (80KB smem). Emits fp16 output (all layers).
// ---------------------------------------------------------------------------
#define WS2 136
#define AS2 20
#define SWH_WORDS (128 * WS2)    // 17408
#define SAH_WORDS (128 * AS2)    //  2560
#define GC_SMEM_BYTES ((SWH_WORDS + SAH_WORDS) * 4)

__device__ __forceinline__ void mma_f16(float c[4],
                                        uint32_t a0, uint32_t a1,
                                        uint32_t a2, uint32_t a3,
                                        uint32_t b0, uint32_t b1)
{
    asm volatile("mma.sync.aligned.m16n8k16.row.col.f32.f16.f16.f32 "
                 "{%0,%1,%2,%3}, {%4,%5,%6,%7}, {%8,%9}, {%0,%1,%2,%3};"
                 : "+f"(c[0]), "+f"(c[1]), "+f"(c[2]), "+f"(c[3])
                 : "r"(a0), "r"(a1), "r"(a2), "r"(a3), "r"(b0), "r"(b1));
}

__global__ __launch_bounds__(256, 2) void gconv_h_kernel(
    const uint4* __restrict__ Ah, const uint4* __restrict__ Xh,
    const float* __restrict__ Wrel, const float* __restrict__ Wroot,
    const float* __restrict__ bias, uint32_t* __restrict__ out16, int do_relu)
{
    extern __shared__ uint32_t smw[];
    uint32_t* sW = smw;               // [k2 0..127][n 0..127] stride 136
    uint32_t* sA = smw + SWH_WORDS;   // [row 0..127][k2 0..15] stride 20

    const int tid  = threadIdx.x;
    const int warp = tid >> 5;
    const int lane = tid & 31;
    const int rowBase = blockIdx.x * 128;

    const int wm = (warp & 3) * 32;   // warp rows [wm, wm+32)
    const int wn = (warp >> 2) * 64;  // warp cols [wn, wn+64)
    const int g8 = lane >> 2;
    const int ak = lane & 3;

    // ---- Stage stacked weights as half2(k even, k odd) ----
    for (int i = tid; i < 4096; i += 256) {
        int k2 = i >> 5;          // 0..127
        int n4 = i & 31;
        const float* r0 = (k2 < 64) ? &Wrel[(2 * k2) * FC + n4 * 4]
                                    : &Wroot[(2 * k2 - 128) * FC + n4 * 4];
        float4 w0 = *(const float4*)r0;
        float4 w1 = *(const float4*)(r0 + FC);
        uint32_t* d = &sW[k2 * WS2 + n4 * 4];
        *(__half2*)&d[0] = __floats2half2_rn(w0.x, w1.x);
        *(__half2*)&d[1] = __floats2half2_rn(w0.y, w1.y);
        *(__half2*)&d[2] = __floats2half2_rn(w0.z, w1.z);
        *(__half2*)&d[3] = __floats2half2_rn(w0.w, w1.w);
    }

    // ---- Stage chunk 0 (k [0,32) of agg) ----
#pragma unroll
    for (int r = 0; r < 2; r++) {
        int idx = tid + r * 256;
        int row = idx >> 2;
        int q   = idx & 3;
        int grow = rowBase + row;
        uint4 v = make_uint4(0, 0, 0, 0);
        if (grow < NN) v = Ah[(size_t)grow * 16 + q];
        uint32_t* d = &sA[row * AS2 + q * 4];
        d[0] = v.x; d[1] = v.y; d[2] = v.z; d[3] = v.w;
    }
    __syncthreads();

    float acc[2][8][4];
#pragma unroll
    for (int t = 0; t < 2; t++)
#pragma unroll
        for (int j = 0; j < 8; j++)
#pragma unroll
            for (int q = 0; q < 4; q++) acc[t][j][q] = 0.f;

    const int ar = (wm + g8) * AS2;

    uint4 pf[2];
#pragma unroll 1
    for (int c = 0; c < 8; c++) {
        if (c < 7) {
            const uint4* src = (c + 1 < 4) ? Ah : Xh;
            int cq = ((c + 1) & 3) * 4;
#pragma unroll
            for (int r = 0; r < 2; r++) {
                int idx = tid + r * 256;
                int row = idx >> 2;
                int q   = idx & 3;
                int grow = rowBase + row;
                pf[r] = (grow < NN) ? src[(size_t)grow * 16 + cq + q]
                                    : make_uint4(0, 0, 0, 0);
            }
        }

#pragma unroll
        for (int s = 0; s < 2; s++) {
            int kl = s * 8;
            uint32_t a00 = sA[ar + kl + ak];
            uint32_t a01 = sA[ar + 8 * AS2 + kl + ak];
            uint32_t a02 = sA[ar + kl + ak + 4];
            uint32_t a03 = sA[ar + 8 * AS2 + kl + ak + 4];
            uint32_t a10 = sA[ar + 16 * AS2 + kl + ak];
            uint32_t a11 = sA[ar + 24 * AS2 + kl + ak];
            uint32_t a12 = sA[ar + 16 * AS2 + kl + ak + 4];
            uint32_t a13 = sA[ar + 24 * AS2 + kl + ak + 4];
            int kg2 = c * 16 + kl;
            const uint32_t* bp = &sW[(kg2 + ak) * WS2 + wn + g8];
            uint32_t b0[8], b1[8];
#pragma unroll
            for (int j = 0; j < 8; j++) {
                b0[j] = bp[j * 8];
                b1[j] = bp[j * 8 + 4 * WS2];
            }
#pragma unroll
            for (int j = 0; j < 8; j++)
                mma_f16(acc[0][j], a00, a01, a02, a03, b0[j], b1[j]);
#pragma unroll
            for (int j = 0; j < 8; j++)
                mma_f16(acc[1][j], a10, a11, a12, a13, b0[j], b1[j]);
        }
        __syncthreads();

        if (c < 7) {
#pragma unroll
            for (int r = 0; r < 2; r++) {
                int idx = tid + r * 256;
                int row = idx >> 2;
                int q   = idx & 3;
                uint32_t* d = &sA[row * AS2 + q * 4];
                d[0] = pf[r].x; d[1] = pf[r].y; d[2] = pf[r].z; d[3] = pf[r].w;
            }
            __syncthreads();
        }
    }

    // ---- Epilogue: bias (+relu); fp16 stores ----
    const int coff = ak * 2;
    const int rbase = rowBase + wm + g8;
#pragma unroll
    for (int t = 0; t < 2; t++) {
        int ra = rbase + t * 16;
        int rb = ra + 8;
#pragma unroll
        for (int j = 0; j < 8; j++) {
            int col = wn + j * 8 + coff;
            float2 bb = *(const float2*)&bias[col];
            float2 o0, o1;
            o0.x = acc[t][j][0] + bb.x; o0.y = acc[t][j][1] + bb.y;
            o1.x = acc[t][j][2] + bb.x; o1.y = acc[t][j][3] + bb.y;
            if (do_relu) {
                o0.x = fmaxf(o0.x, 0.f); o0.y = fmaxf(o0.y, 0.f);
                o1.x = fmaxf(o1.x, 0.f); o1.y = fmaxf(o1.y, 0.f);
            }
            if (ra < NN)
                *(__half2*)&out16[(size_t)ra * 64 + (col >> 1)]
                    = __floats2half2_rn(o0.x, o0.y);
            if (rb < NN)
                *(__half2*)&out16[(size_t)rb * 64 + (col >> 1)]
                    = __floats2half2_rn(o1.x, o1.y);
        }
    }
}

// ---------------------------------------------------------------------------
// Fused mean-pool + classifier, fp16 input (batch sorted -> contiguous ranges)
// ---------------------------------------------------------------------------
__global__ void poolfinal_kernel(const __half* __restrict__ h16,
                                 const void* __restrict__ batch,
                                 const float* __restrict__ Wlin,
                                 const float* __restrict__ blin,
                                 float* __restrict__ out)
{
    __shared__ float sp[FC];
    __shared__ int bounds[2];
    int g = blockIdx.x;
    int t = threadIdx.x;
    int is64 = g_is64;

    if (t < 2) {
        long long target = g + t;
        int lo = 0, hi = NN;
        while (lo < hi) {
            int mid = (lo + hi) >> 1;
            if (load_idx(batch, mid, is64) < target) lo = mid + 1;
            else hi = mid;
        }
        bounds[t] = lo;
    }
    __syncthreads();
    int lo = bounds[0], hi = bounds[1];

    float s = 0.f;
    for (int n = lo; n < hi; n++)
        s += __half2float(h16[(size_t)n * FC + t]);
    float inv = 1.0f / fmaxf((float)(hi - lo), 1.0f);
    sp[t] = s * inv;
    __syncthreads();

    if (t < NOUT) {
        float acc = blin[t];
#pragma unroll 16
        for (int k = 0; k < FC; k++)
            acc += sp[k] * Wlin[k * NOUT + t];
        out[g * NOUT + t] = acc;
    }
}

// ---------------------------------------------------------------------------
extern "C" void kernel_launch(void* const* d_in, const int* in_sizes, int n_in,
                              void* d_out, int out_size)
{
    const float* x     = (const float*)d_in[0];
    const void*  ei    = d_in[1];
    const void*  batch = d_in[2];
    const float* W1r = (const float*)d_in[3];
    const float* b1  = (const float*)d_in[4];
    const float* W1s = (const float*)d_in[5];
    const float* W2r = (const float*)d_in[6];
    const float* b2  = (const float*)d_in[7];
    const float* W2s = (const float*)d_in[8];
    const float* W3r = (const float*)d_in[9];
    const float* b3  = (const float*)d_in[10];
    const float* W3s = (const float*)d_in[11];
    const float* Wl  = (const float*)d_in[12];
    const float* bl  = (const float*)d_in[13];
    float* out = (float*)d_out;

    cudaFuncSetAttribute(gconv_h_kernel,
                         cudaFuncAttributeMaxDynamicSharedMemorySize,
                         GC_SMEM_BYTES);

    uint2 *agg16, *f16a, *f16b;
    int *rowptr, *cursor, *esrc, *part;
    cudaGetSymbolAddress((void**)&agg16,  g_agg16);
    cudaGetSymbolAddress((void**)&f16a,   g_f16a);
    cudaGetSymbolAddress((void**)&f16b,   g_f16b);
    cudaGetSymbolAddress((void**)&rowptr, g_rowptr);
    cudaGetSymbolAddress((void**)&cursor, g_cursor);
    cudaGetSymbolAddress((void**)&esrc,   g_esrc);
    cudaGetSymbolAddress((void**)&part,   g_part);

    const int nblocks8 = (NN + 7) / 8;
    const int gblocks  = (NN + 127) / 128;
    const int cblocks  = (NN * 32 + 255) / 256;

    detect_kernel<<<1, 512>>>((const long long*)ei);

    // ---- CSR build ----
    cudaMemsetAsync(rowptr, 0, NSCAN * sizeof(int));
    hist_kernel<<<2048, 256>>>(ei, rowptr);
    scanA_kernel<<<NBLK, SCAN_BLK>>>(rowptr, part);
    scanC_kernel<<<NBLK, SCAN_BLK>>>(rowptr, part, cursor);
    fill_kernel<<<2048, 256>>>(ei, cursor, esrc);

    // fp16 copy of x
    cvt16_kernel<<<cblocks, 256>>>((const float4*)x, f16a);

    // Layer 1: f16a -> f16b
    gather_h_kernel<<<nblocks8, 256>>>(f16a, rowptr, esrc, agg16);
    gconv_h_kernel<<<gblocks, 256, GC_SMEM_BYTES>>>(
        (const uint4*)agg16, (const uint4*)f16a, W1r, W1s, b1,
        (uint32_t*)f16b, 1);
    // Layer 2: f16b -> f16a
    gather_h_kernel<<<nblocks8, 256>>>(f16b, rowptr, esrc, agg16);
    gconv_h_kernel<<<gblocks, 256, GC_SMEM_BYTES>>>(
        (const uint4*)agg16, (const uint4*)f16b, W2r, W2s, b2,
        (uint32_t*)f16a, 1);
    // Layer 3: f16a -> f16b (fp16 output, no relu)
    gather_h_kernel<<<nblocks8, 256>>>(f16a, rowptr, esrc, agg16);
    gconv_h_kernel<<<gblocks, 256, GC_SMEM_BYTES>>>(
        (const uint4*)agg16, (const uint4*)f16a, W3r, W3s, b3,
        (uint32_t*)f16b, 0);

    // Fused mean-pool + classifier (fp16 input)
    poolfinal_kernel<<<NG, FC>>>((const __half*)f16b, batch, Wl, bl, out);
}